// round 2
// baseline (speedup 1.0000x reference)
#include <cuda_runtime.h>
#include <math.h>

#define B_  16
#define L_  1024
#define C_  128
#define H_  512
#define LC_ (L_*C_)      // 131072
#define M_  (B_*L_)      // 16384

// ---------------- device scratch (no allocations allowed) ----------------
__device__ float g_h  [M_*H_];        // 32 MB  hidden activations
__device__ float g_eps[M_*C_];        // 8 MB   epsilon prediction
__device__ float g_za [M_*C_];        // ping
__device__ float g_zb [M_*C_];        // pong
__device__ float g_ent[LC_];          // entropy map [L,C]
__device__ float g_p1[(L_/2)*(C_/2)]; // pooled w=2
__device__ float g_p2[(L_/4)*(C_/4)]; // pooled w=4
__device__ float g_p3[(L_/8)*(C_/8)]; // pooled w=8
__device__ float g_part[1024];        // 512 block partials x {sum, sumsq}
__device__ float g_T[4];              // per-scale thresholds (K-th largest)
__device__ float g_stats[2];          // global sum, sumsq of obs_err

// ---------------- helpers ----------------
__device__ __forceinline__ float gelu_f(float x) {
    // jax.nn.gelu default (tanh approximation)
    float x3 = x * x * x;
    float u  = 0.7978845608028654f * (x + 0.044715f * x3);
    return 0.5f * x * (1.0f + tanhf(u));
}

// ---------------- GEMM: out[M,N] = act(A[M,K] @ W[K,N] + bias (+ t*tw)) ----
// BM=128, BN=64, BK=16, 256 threads, 8x4 per thread. M,N,K all divisible.
template<bool GELU>
__global__ __launch_bounds__(256)
void gemm_k(const float* __restrict__ A, const float* __restrict__ W,
            const float* __restrict__ bias, const float* __restrict__ tw,
            float t_feat, float* __restrict__ out, int N, int K)
{
    const int BM = 128, BN = 64, BK = 16;
    __shared__ float As[BK][BM + 4];   // padded to 132 (16B-aligned rows, de-conflicted stores)
    __shared__ float Bs[BK][BN];

    const int tid = threadIdx.x;
    const int m0 = blockIdx.y * BM, n0 = blockIdx.x * BN;
    const int ty = tid >> 4, tx = tid & 15;
    const int mo = ty * 8, no = tx * 4;

    float acc[8][4];
#pragma unroll
    for (int i = 0; i < 8; i++)
#pragma unroll
        for (int j = 0; j < 4; j++) acc[i][j] = 0.0f;

    for (int k0 = 0; k0 < K; k0 += BK) {
        // A tile: 128x16 = 512 float4, 2 per thread. Transposed into As[k][m].
#pragma unroll
        for (int r = 0; r < 2; r++) {
            int f   = tid + r * 256;
            int row = f >> 2, c4 = f & 3;
            float4 v = *(const float4*)(A + (size_t)(m0 + row) * K + k0 + c4 * 4);
            As[c4 * 4 + 0][row] = v.x;
            As[c4 * 4 + 1][row] = v.y;
            As[c4 * 4 + 2][row] = v.z;
            As[c4 * 4 + 3][row] = v.w;
        }
        // B tile: 16x64 = 256 float4, 1 per thread.
        {
            int kr = tid >> 4, c4 = tid & 15;
            *(float4*)(&Bs[kr][c4 * 4]) =
                *(const float4*)(W + (size_t)(k0 + kr) * N + n0 + c4 * 4);
        }
        __syncthreads();

#pragma unroll
        for (int kk = 0; kk < BK; kk++) {
            float4 a0 = *(float4*)(&As[kk][mo]);
            float4 a1 = *(float4*)(&As[kk][mo + 4]);
            float4 bv = *(float4*)(&Bs[kk][no]);
            float a[8] = {a0.x, a0.y, a0.z, a0.w, a1.x, a1.y, a1.z, a1.w};
            float b[4] = {bv.x, bv.y, bv.z, bv.w};
#pragma unroll
            for (int i = 0; i < 8; i++)
#pragma unroll
                for (int j = 0; j < 4; j++)
                    acc[i][j] = fmaf(a[i], b[j], acc[i][j]);
        }
        __syncthreads();
    }

    // epilogue
    float bz[4];
#pragma unroll
    for (int j = 0; j < 4; j++) {
        int gn = n0 + no + j;
        bz[j] = bias[gn];
        if (GELU) bz[j] += t_feat * tw[gn];
    }
#pragma unroll
    for (int i = 0; i < 8; i++) {
        int gm = m0 + mo + i;
        float4 o;
        float v0 = acc[i][0] + bz[0];
        float v1 = acc[i][1] + bz[1];
        float v2 = acc[i][2] + bz[2];
        float v3 = acc[i][3] + bz[3];
        if (GELU) { v0 = gelu_f(v0); v1 = gelu_f(v1); v2 = gelu_f(v2); v3 = gelu_f(v3); }
        o.x = v0; o.y = v1; o.z = v2; o.w = v3;
        *(float4*)(out + (size_t)gm * N + n0 + no) = o;
    }
}

// ---------------- entropy map + obs_err partial stats ----------------
__global__ __launch_bounds__(256)
void stats_k(const float* __restrict__ z, const float* __restrict__ y,
             const float* __restrict__ msk)
{
    int tid = threadIdx.x;
    int i = blockIdx.x * 256 + tid;   // i < LC_

    float sa = 0.0f;
#pragma unroll
    for (int b = 0; b < B_; b++) sa += fabsf(g_eps[(size_t)b * LC_ + i]);
    g_ent[i] = sa * (1.0f / B_);

    float s = 0.0f, sq = 0.0f;
#pragma unroll
    for (int b = 0; b < B_; b++) {
        size_t o = (size_t)b * LC_ + i;
        float e = (z[o] - y[o]) * msk[o];
        s += e; sq += e * e;
    }
    __shared__ float rs[256], rq[256];
    rs[tid] = s; rq[tid] = sq;
    __syncthreads();
    for (int st = 128; st > 0; st >>= 1) {
        if (tid < st) { rs[tid] += rs[tid + st]; rq[tid] += rq[tid + st]; }
        __syncthreads();
    }
    if (tid == 0) { g_part[blockIdx.x] = rs[0]; g_part[512 + blockIdx.x] = rq[0]; }
}

// ---------------- hierarchical pooling (all three levels, one launch) -----
__global__ __launch_bounds__(256)
void pool_k()
{
    int t = blockIdx.x * 256 + threadIdx.x;
    int w, idx; float* dst;
    if      (t < 32768) { w = 2; dst = g_p1; idx = t; }
    else if (t < 40960) { w = 4; dst = g_p2; idx = t - 32768; }
    else if (t < 43008) { w = 8; dst = g_p3; idx = t - 40960; }
    else return;
    int Cs = C_ / w;
    int pr = idx / Cs, pc = idx % Cs;
    float s = 0.0f;
    for (int a = 0; a < w; a++)
        for (int b = 0; b < w; b++)
            s += g_ent[(pr * w + a) * C_ + pc * w + b];
    dst[idx] = s / (float)(w * w);
}

// ---------------- per-scale K-th largest (radix select) + var finalize ----
__global__ __launch_bounds__(256)
void select_k()
{
    int bs = blockIdx.x;
    int tid = threadIdx.x;

    if (bs == 4) {   // finalize obs_err stats deterministically
        __shared__ float rs[256], rq[256];
        rs[tid] = g_part[tid] + g_part[tid + 256];
        rq[tid] = g_part[512 + tid] + g_part[512 + tid + 256];
        __syncthreads();
        for (int st = 128; st > 0; st >>= 1) {
            if (tid < st) { rs[tid] += rs[tid + st]; rq[tid] += rq[tid + st]; }
            __syncthreads();
        }
        if (tid == 0) { g_stats[0] = rs[0]; g_stats[1] = rq[0]; }
        return;
    }

    const float* data; int n, K;
    switch (bs) {
        case 0: data = g_ent; n = 131072; K = 26214; break;  // int(0.2*131072)
        case 1: data = g_p1;  n = 32768;  K = 6553;  break;
        case 2: data = g_p2;  n = 8192;   K = 1638;  break;
        default:data = g_p3;  n = 2048;   K = 409;   break;
    }

    __shared__ unsigned hist[256];
    __shared__ unsigned s_pref, s_k;
    unsigned pref = 0, kk = (unsigned)K;

    for (int p = 0; p < 4; p++) {
        int shift = 24 - 8 * p;
        unsigned mask_hi = (p == 0) ? 0u : (0xFFFFFFFFu << (32 - 8 * p));
        hist[tid] = 0;
        __syncthreads();
        for (int i = tid; i < n; i += 256) {
            unsigned u = __float_as_uint(data[i]);   // values >= 0: bits are order-preserving
            if ((u & mask_hi) == pref) atomicAdd(&hist[(u >> shift) & 255], 1u);
        }
        __syncthreads();
        if (tid == 0) {
            unsigned cum = 0; int sel = 0;
            for (int b = 255; b >= 0; b--) {
                unsigned c = hist[b];
                if (cum + c >= kk) { sel = b; break; }
                cum += c;
            }
            s_pref = pref | ((unsigned)sel << shift);
            s_k = kk - cum;
        }
        __syncthreads();
        pref = s_pref; kk = s_k;
        __syncthreads();
    }
    if (tid == 0) g_T[bs] = __uint_as_float(pref);
}

// ---------------- final update: finest selected scale wins ----------------
__global__ __launch_bounds__(256)
void update_k(const float* __restrict__ z, const float* __restrict__ y,
              const float* __restrict__ msk, float* __restrict__ out,
              float base_a, float base_b, float h_lam)
{
    int i = blockIdx.x * 256 + threadIdx.x;  // i < LC_
    int l = i / C_, c = i % C_;

    int sfound = -1; float ent = 0.0f;
    float v0 = g_ent[i];
    if (v0 >= g_T[0]) { sfound = 0; ent = v0; }
    else {
        float v1 = g_p1[(l >> 1) * (C_ / 2) + (c >> 1)];
        if (v1 >= g_T[1]) { sfound = 1; ent = v1; }
        else {
            float v2 = g_p2[(l >> 2) * (C_ / 4) + (c >> 2)];
            if (v2 >= g_T[2]) { sfound = 2; ent = v2; }
            else {
                float v3 = g_p3[(l >> 3) * (C_ / 8) + (c >> 3)];
                if (v3 >= g_T[3]) { sfound = 3; ent = v3; }
            }
        }
    }

    if (sfound < 0) {
#pragma unroll
        for (int b = 0; b < B_; b++) {
            size_t o = (size_t)b * LC_ + i;
            out[o] = z[o];
        }
        return;
    }

    const float invN = 1.0f / (float)(B_ * LC_);
    float mean = g_stats[0] * invN;
    float var  = g_stats[1] * invN - mean * mean;
    float inv_d = 1.0f / (var + 1e-8f);

    float om1 = (ent > 0.1f ? 1.0f : 0.0f) + (ent > 0.5f ? 1.0f : 0.0f); // order-1
    float corr = 1.0f + om1 * 0.5f * h_lam
               + om1 * (om1 - 1.0f) * (1.0f / 6.0f) * h_lam * h_lam;
    float gs = 2.0f * ent / (ent + 1.0f);   // G0 = 2
    float bb = base_b * corr;

#pragma unroll
    for (int b = 0; b < B_; b++) {
        size_t o = (size_t)b * LC_ + i;
        float zv = z[o];
        float gd = -(zv - y[o]) * msk[o] * inv_d;
        out[o] = base_a * zv - bb * g_eps[o] + gs * gd;
    }
}

// ---------------- host driver ----------------
extern "C" void kernel_launch(void* const* d_in, const int* in_sizes, int n_in,
                              void* d_out, int out_size)
{
    const float* y   = (const float*)d_in[0];
    const float* msk = (const float*)d_in[1];
    const float* z0  = (const float*)d_in[2];
    const float* W1  = (const float*)d_in[3];
    const float* b1  = (const float*)d_in[4];
    const float* W2  = (const float*)d_in[5];
    const float* b2  = (const float*)d_in[6];
    const float* tw  = (const float*)d_in[7];

    // Diffusion schedule, replicated in f32 like jnp (linspace + cumprod).
    static float ac[1000];
    {
        float run = 1.0f;
        for (int i = 0; i < 1000; i++) {
            float beta = 1e-4f + (0.02f - 1e-4f) * ((float)i / 999.0f);
            run *= (1.0f - beta);
            ac[i] = run;
        }
    }
    auto alpha_at = [&](int i) { return sqrtf(ac[i]); };
    auto sigma_at = [&](int i) { return sqrtf(1.0f - ac[i]); };
    auto lam_at   = [&](int i) { return logf(alpha_at(i)) - logf(sigma_at(i)); };

    float *p_h, *p_eps, *p_za, *p_zb;
    cudaGetSymbolAddress((void**)&p_h,   g_h);
    cudaGetSymbolAddress((void**)&p_eps, g_eps);
    cudaGetSymbolAddress((void**)&p_za,  g_za);
    cudaGetSymbolAddress((void**)&p_zb,  g_zb);

    const float* zin[4]  = { z0,  p_za, p_zb, p_za };
    float*       zout[4] = { p_za, p_zb, p_za, (float*)d_out };

    const int step = 1000 / 4;
    dim3 grid1(H_ / 64, M_ / 128);   // (8, 128)
    dim3 grid2(C_ / 64, M_ / 128);   // (2, 128)

    for (int si = 0; si < 4; si++) {
        int k  = 999 - si * step;
        int kp = k - step; if (kp < 0) kp = 0;
        float t_feat = (float)k / 1000.0f;
        float h_lam  = lam_at(kp) - lam_at(k);
        float base_a = alpha_at(kp) / alpha_at(k);
        float base_b = sigma_at(kp) * (expf(h_lam) - 1.0f);

        gemm_k<true ><<<grid1, 256>>>(zin[si], W1, b1, tw, t_feat, p_h,   H_, C_);
        gemm_k<false><<<grid2, 256>>>(p_h,     W2, b2, tw, 0.0f,   p_eps, C_, H_);
        stats_k <<<LC_ / 256, 256>>>(zin[si], y, msk);
        pool_k  <<<168, 256>>>();
        select_k<<<5, 256>>>();
        update_k<<<LC_ / 256, 256>>>(zin[si], y, msk, zout[si], base_a, base_b, h_lam);
    }
}